// round 10
// baseline (speedup 1.0000x reference)
#include <cuda_runtime.h>
#include <cstdint>

typedef unsigned long long ull;

#define Bsz 1024
#define Tt 64
#define Dd 128
#define Hh 128
#define ATT 64
#define HOR 24
#define G 8
#define NCTAS (Bsz/G)
#define NTHR 512

// ---------------- device scratch ----------------
__device__ float g_WihT[Dd * 4 * Hh];   // [k][512o]
__device__ float g_WhhT[Hh * 4 * Hh];   // [k][512o]
__device__ float g_WhhTd[Hh * 4 * Hh];  // [k][512o]
__device__ float g_hid[(size_t)Bsz * Tt * Hh];   // [b][t][h]
__device__ float g_proj[(size_t)Bsz * ATT * Tt]; // [b][a][t]

// ---------------- helpers ----------------
__device__ __forceinline__ float tanh_fast(float x) {
    float y; asm("tanh.approx.f32 %0, %1;" : "=f"(y) : "f"(x)); return y;
}
__device__ __forceinline__ float sigm(float x) { return 1.f / (1.f + __expf(-x)); }
__device__ __forceinline__ float tanh_acc(float x) {
    float ax = fabsf(x);
    float e = __expf(-2.f * ax);
    float t = (1.f - e) / (1.f + e);
    return copysignf(t, x);
}
__device__ __forceinline__ ull pack2(float lo, float hi) {
    ull r; asm("mov.b64 %0, {%1,%2};" : "=l"(r) : "f"(lo), "f"(hi)); return r;
}
__device__ __forceinline__ float2 unpack2(ull v) {
    float2 r; asm("mov.b64 {%0,%1}, %2;" : "=f"(r.x), "=f"(r.y) : "l"(v)); return r;
}
__device__ __forceinline__ void ffma2(ull &d, ull a, ull b) {
    asm("fma.rn.f32x2 %0, %1, %2, %0;" : "+l"(d) : "l"(a), "l"(b));
}
__device__ __forceinline__ void barw(int id) {  // warpgroup barrier (128 thr)
    asm volatile("bar.sync %0, 128;" :: "r"(id) : "memory");
}

// ---- non-duplicated-activation GEMM over NK k-values ----
// Wbase: weight ull array, k-th o-pair at Wbase[k*256] (pre-offset by o-pair)
// act:   plain activations, g-th row at act + g*128 (k-local index 0..NK-1)
// dst:   partial gate array, float2 at dst + g*512 + 2*opi
template<int NK>
__device__ __forceinline__ void gemm_nd(const ull* __restrict__ Wbase,
                                        const float* __restrict__ act,
                                        float* __restrict__ dst, int opi) {
    ull acc[8];
    #pragma unroll
    for (int g = 0; g < 8; ++g) acc[g] = 0ULL;
    #pragma unroll 2
    for (int kb = 0; kb < NK; kb += 4) {
        ull w0 = Wbase[(kb + 0) * 256];
        ull w1 = Wbase[(kb + 1) * 256];
        ull w2 = Wbase[(kb + 2) * 256];
        ull w3 = Wbase[(kb + 3) * 256];
        #pragma unroll
        for (int g = 0; g < 8; ++g) {
            float4 a = *(const float4*)(act + g * 128 + kb);
            ffma2(acc[g], w0, pack2(a.x, a.x));
            ffma2(acc[g], w1, pack2(a.y, a.y));
            ffma2(acc[g], w2, pack2(a.z, a.z));
            ffma2(acc[g], w3, pack2(a.w, a.w));
        }
    }
    #pragma unroll
    for (int g = 0; g < 8; ++g) {
        float2 r2 = unpack2(acc[g]);
        *(float2*)(dst + g * 512 + 2 * opi) = r2;
    }
}

// ---------------- prologue: transpose LSTM weights ----------------
__global__ void transpose_k(const float* __restrict__ Wih,
                            const float* __restrict__ Whh,
                            const float* __restrict__ Wdh) {
    int i = blockIdx.x * blockDim.x + threadIdx.x;
    if (i < 512 * 128) {
        int o = i >> 7, k = i & 127;
        g_WihT[k * 512 + o]  = Wih[i];
        g_WhhT[k * 512 + o]  = Whh[i];
        g_WhhTd[k * 512 + o] = Wdh[i];
    }
}

// smem float offsets (all multiples of 4)
#define OFF_W      0
#define SZ_W       24704              // 64*386 (enc stride 258, dec 386)
#define OFF_H      (OFF_W + SZ_W)
#define OFF_C      (OFF_H + 1024)
#define OFF_X      (OFF_C + 1024)     // x_tilde (enc) / context (dec) / proj staging
#define OFF_BASE   (OFF_X + 1024)
#define OFF_SC     (OFF_BASE + 512)
#define OFF_GA     (OFF_SC + 512)     // Wih partial kh=0
#define OFF_GB     (OFF_GA + 4096)    // Whh full
#define OFF_GC     (OFF_GB + 4096)    // Wih partial kh=1
#define OFF_BIAS   (OFF_GC + 4096)
#define OFF_WEB    (OFF_BIAS + 512)
#define OFF_WV     (OFF_WEB + 64)     // (w_feat, ve_w) pairs, 128 floats
#define OFF_WDB    (OFF_WV + 128)
#define OFF_VDW    (OFF_WDB + 64)
#define OFF_DWIH   (OFF_VDW + 64)
#define OFF_FCW    (OFF_DWIH + 512)
#define OFF_YH     (OFF_FCW + 320)
#define OFF_YPREV  (OFF_YH + 512)
#define SMEM_FLOATS (OFF_YPREV + 8)
#define SMEM_BYTES  (SMEM_FLOATS * 4)

__global__ void __launch_bounds__(NTHR, 1)
darnn_kernel(const float* __restrict__ X,        const float* __restrict__ y_hist,
             const float* __restrict__ We_w,     const float* __restrict__ We_b,
             const float* __restrict__ ve_w,     const float* __restrict__ ve_b,
             const float* __restrict__ enc_bih,  const float* __restrict__ enc_bhh,
             const float* __restrict__ dec_Wih,  const float* __restrict__ dec_bih,
             const float* __restrict__ dec_bhh,
             const float* __restrict__ Wd_w,     const float* __restrict__ Wd_b,
             const float* __restrict__ vd_w,     const float* __restrict__ vd_b,
             const float* __restrict__ fc_w,     const float* __restrict__ fc_b,
             float* __restrict__ out) {
    extern __shared__ float sm[];
    float* sW      = sm + OFF_W;
    float* s_h     = sm + OFF_H;
    float* s_c     = sm + OFF_C;
    float* s_x     = sm + OFF_X;
    float* s_base  = sm + OFF_BASE;
    float* s_sc    = sm + OFF_SC;
    float* s_gA    = sm + OFF_GA;
    float* s_gB    = sm + OFF_GB;
    float* s_gC    = sm + OFF_GC;
    float* s_bias  = sm + OFF_BIAS;
    float* s_Web   = sm + OFF_WEB;
    float* s_wv    = sm + OFF_WV;
    float* s_Wdb   = sm + OFF_WDB;
    float* s_vdw   = sm + OFF_VDW;
    float* s_dWih  = sm + OFF_DWIH;
    float* s_fcw   = sm + OFF_FCW;
    float* s_yh    = sm + OFF_YH;
    float* s_yprev = sm + OFF_YPREV;

    const int tid  = threadIdx.x;
    const int lane = tid & 31;
    const int wrp  = tid >> 5;
    const int la   = lane;
    const int b0   = blockIdx.x * G;
    const int gt   = tid - 256;         // gemm-warp thread id (warps 8-15)
    const int op4  = tid & 255;         // Wih-phase o-pair
    const int kh4  = tid >> 8;          // Wih-phase k-half
    const int gU   = tid >> 6;          // update: batch row
    const int i2   = (tid & 63) * 2;    // update: unit pair
    const int gg   = tid >> 7;          // proj-phase warpgroup
    const int wt   = tid & 127;
    const int g0p  = gg * 2, g1p = g0p + 1;
    const int glp  = g0p + (wt >> 6);
    const int a63  = tid & 63;
    const int WB   = 1 + gg;

    const float ve_b_r = ve_b[0];

    // ---------- preload (encoder) ----------
    for (int i = tid; i < 64 * 257; i += NTHR) {
        int r = i / 257, c = i - r * 257;
        sW[r * 258 + c] = We_w[i];
    }
    if (tid < 512) s_bias[tid] = enc_bih[tid] + enc_bhh[tid];
    if (tid < 64) {
        s_Web[tid] = We_b[tid];
        ((float2*)s_wv)[tid] = make_float2(We_w[tid * 257 + 256], ve_w[tid]);
    }
    if (tid < G * Tt) s_yh[tid] = y_hist[b0 * Tt + tid];
    for (int i = tid; i < 1024; i += NTHR) { s_h[i] = 0.f; s_c[i] = 0.f; }
    __syncthreads();

    const ull* WihP  = reinterpret_cast<const ull*>(g_WihT);   // [k][256 o-pairs]
    const ull* WhhP  = reinterpret_cast<const ull*>(g_WhhT);
    const ull* WhhPd = reinterpret_cast<const ull*>(g_WhhTd);

    // ================= ENCODER: 64 steps =================
    for (int t = 0; t < Tt; ++t) {
        if (wrp < 8) {
            const int r = wrp;   // batch row
            // ---- E2: base[a] for a = la, la+32 (k-paired smem weights) ----
            {
                const ull* Wr0 = (const ull*)(sW + la * 258);
                const ull* Wr1 = (const ull*)(sW + (la + 32) * 258);
                const ull* hg2 = (const ull*)(s_h + r * 128);
                const ull* cg2 = (const ull*)(s_c + r * 128);
                ull a0A = pack2(s_Web[la], 0.f), a0B = 0ULL;
                ull a1A = pack2(s_Web[la + 32], 0.f), a1B = 0ULL;
                #pragma unroll 4
                for (int j = 0; j < 64; j += 2) {
                    ull h0 = hg2[j], h1 = hg2[j + 1];
                    ffma2(a0A, Wr0[j], h0); ffma2(a0B, Wr0[j + 1], h1);
                    ffma2(a1A, Wr1[j], h0); ffma2(a1B, Wr1[j + 1], h1);
                }
                #pragma unroll 4
                for (int j = 0; j < 64; j += 2) {
                    ull c0 = cg2[j], c1 = cg2[j + 1];
                    ffma2(a0A, Wr0[64 + j], c0); ffma2(a0B, Wr0[64 + j + 1], c1);
                    ffma2(a1A, Wr1[64 + j], c0); ffma2(a1B, Wr1[64 + j + 1], c1);
                }
                float2 p = unpack2(a0A), q = unpack2(a0B);
                s_base[r * 64 + la] = (p.x + q.x) + (p.y + q.y);
                p = unpack2(a1A); q = unpack2(a1B);
                s_base[r * 64 + la + 32] = (p.x + q.x) + (p.y + q.y);
            }
            __syncwarp();
            // ---- E3+E4: scores + softmax (warp) + x_tilde (plain) ----
            {
                const float* Xg = X + ((size_t)(b0 + r) * Tt + t) * Dd;
                float xv0 = Xg[la], xv1 = Xg[la + 32], xv2 = Xg[la + 64], xv3 = Xg[la + 96];
                float s0 = ve_b_r, s1 = ve_b_r, s2 = ve_b_r, s3 = ve_b_r;
                const float* bg = s_base + r * 64;
                const float2* wv = (const float2*)s_wv;
                #pragma unroll 8
                for (int a = 0; a < 64; ++a) {
                    float ba = bg[a];
                    float2 w = wv[a];   // (w_feat, ve_w)
                    s0 = fmaf(w.y, tanh_fast(fmaf(xv0, w.x, ba)), s0);
                    s1 = fmaf(w.y, tanh_fast(fmaf(xv1, w.x, ba)), s1);
                    s2 = fmaf(w.y, tanh_fast(fmaf(xv2, w.x, ba)), s2);
                    s3 = fmaf(w.y, tanh_fast(fmaf(xv3, w.x, ba)), s3);
                }
                float m = fmaxf(fmaxf(s0, s1), fmaxf(s2, s3));
                #pragma unroll
                for (int o = 16; o; o >>= 1) m = fmaxf(m, __shfl_xor_sync(0xffffffffu, m, o));
                float e0 = __expf(s0 - m), e1 = __expf(s1 - m);
                float e2 = __expf(s2 - m), e3 = __expf(s3 - m);
                float ss = (e0 + e1) + (e2 + e3);
                #pragma unroll
                for (int o = 16; o; o >>= 1) ss += __shfl_xor_sync(0xffffffffu, ss, o);
                float inv = 1.f / ss;
                float* xt = s_x + r * 128;
                xt[la]      = xv0 * e0 * inv;
                xt[la + 32] = xv1 * e1 * inv;
                xt[la + 64] = xv2 * e2 * inv;
                xt[la + 96] = xv3 * e3 * inv;
            }
        } else {
            // ---- Whh · h -> s_gB (full k=128), nondup acts ----
            gemm_nd<128>(WhhP + gt, s_h, s_gB, gt);
        }
        __syncthreads();
        // ---- Wih · x_tilde : (op4, kh4) split, nondup acts ----
        gemm_nd<64>(WihP + kh4 * 64 * 256 + op4,
                    s_x + kh4 * 64,
                    kh4 ? s_gC : s_gA, op4);
        __syncthreads();
        // ---- E6: LSTM update, 2 units per thread ----
        {
            const float2* gA2 = (const float2*)(s_gA + gU * 512);
            const float2* gB2 = (const float2*)(s_gB + gU * 512);
            const float2* gC2 = (const float2*)(s_gC + gU * 512);
            const float2* b2  = (const float2*)s_bias;
            const int h2i = i2 >> 1;
            float pre[4][2];
            #pragma unroll
            for (int q = 0; q < 4; ++q) {
                int idx = q * 64 + h2i;
                float2 vA = gA2[idx], vB = gB2[idx], vC = gC2[idx], vb = b2[idx];
                pre[q][0] = ((vA.x + vB.x) + (vC.x + vb.x));
                pre[q][1] = ((vA.y + vB.y) + (vC.y + vb.y));
            }
            float hh[2];
            #pragma unroll
            for (int j = 0; j < 2; ++j) {
                float ig = sigm(pre[0][j]);
                float fg = sigm(pre[1][j]);
                float gv = tanh_acc(pre[2][j]);
                float og = sigm(pre[3][j]);
                float c2 = fmaf(fg, s_c[gU * 128 + i2 + j], ig * gv);
                float h2 = og * tanh_acc(c2);
                s_c[gU * 128 + i2 + j] = c2;
                s_h[gU * 128 + i2 + j] = h2;
                hh[j] = h2;
            }
            *(float2*)(g_hid + ((size_t)(b0 + gU) * Tt + t) * Hh + i2) = make_float2(hh[0], hh[1]);
        }
        __syncthreads();
    }

    // ================= enc_proj =================
    for (int i = tid; i < 64 * 384; i += NTHR) {
        int r = i / 384, c = i - r * 384;
        sW[r * 386 + c] = Wd_w[i];
    }
    __syncthreads();
    for (int t = 0; t < Tt; ++t) {
        s_x[g0p * 128 + wt] = g_hid[((size_t)(b0 + g0p) * Tt + t) * Hh + wt];
        s_x[g1p * 128 + wt] = g_hid[((size_t)(b0 + g1p) * Tt + t) * Hh + wt];
        barw(WB);
        {
            const ull* Wr2 = (const ull*)(sW + a63 * 386);
            const ull* hg2 = (const ull*)(s_x + glp * 128);
            ull aA = 0ULL, aB = 0ULL;
            #pragma unroll 8
            for (int j = 0; j < 64; j += 2) {
                ffma2(aA, Wr2[j], hg2[j]);
                ffma2(aB, Wr2[j + 1], hg2[j + 1]);
            }
            float2 ra = unpack2(aA), rb = unpack2(aB);
            g_proj[((size_t)(b0 + glp)) * ATT * Tt + a63 * Tt + t] = (ra.x + rb.x) + (ra.y + rb.y);
        }
        barw(WB);
    }

    // ---------- preload (decoder) ----------
    __syncthreads();
    if (tid < 512) {
        s_bias[tid] = dec_bih[tid] + dec_bhh[tid];
        s_dWih[tid] = dec_Wih[tid];
    }
    if (tid < 64) { s_Wdb[tid] = Wd_b[tid]; s_vdw[tid] = vd_w[tid]; }
    if (tid < 320) s_fcw[tid] = fc_w[tid];
    for (int i = tid; i < 1024; i += NTHR) { s_h[i] = 0.f; s_c[i] = 0.f; }
    if (tid < G) s_yprev[tid] = s_yh[tid * Tt + Tt - 1];
    const float vd_b_r = vd_b[0];
    const float fc_b_r = fc_b[0];
    __syncthreads();

    // D7 helper
    auto do_D7 = [&](int s) {
        const int r = wrp;
        float acc = 0.f;
        #pragma unroll
        for (int it = 0; it < 10; ++it) {
            int idx = lane + it * 32;
            float v;
            if (idx < 128)      v = s_h[r * 128 + idx];
            else if (idx < 256) v = s_x[r * 128 + idx - 128];
            else                v = s_yh[r * 64 + idx - 256];
            acc = fmaf(s_fcw[idx], v, acc);
        }
        #pragma unroll
        for (int o = 16; o; o >>= 1) acc += __shfl_xor_sync(0xffffffffu, acc, o);
        if (lane == 0) {
            float ov = acc + fc_b_r;
            s_yprev[r] = ov;
            out[(b0 + r) * HOR + s] = ov;
        }
    };

    // ================= DECODER: 24 steps =================
    for (int s = 0; s < HOR; ++s) {
        if (wrp < 8) {
            const int r = wrp;
            if (s > 0) do_D7(s - 1);
            // ---- D1: dc[a] for a = la, la+32 ----
            {
                const ull* W0d = (const ull*)(sW + la * 386 + 128);
                const ull* W0c = (const ull*)(sW + la * 386 + 256);
                const ull* W1d = (const ull*)(sW + (la + 32) * 386 + 128);
                const ull* W1c = (const ull*)(sW + (la + 32) * 386 + 256);
                const ull* dg2 = (const ull*)(s_h + r * 128);
                const ull* cg2 = (const ull*)(s_c + r * 128);
                ull a0A = pack2(s_Wdb[la], 0.f), a0B = 0ULL;
                ull a1A = pack2(s_Wdb[la + 32], 0.f), a1B = 0ULL;
                #pragma unroll 4
                for (int j = 0; j < 64; j += 2) {
                    ull d0 = dg2[j], d1 = dg2[j + 1];
                    ffma2(a0A, W0d[j], d0); ffma2(a0B, W0d[j + 1], d1);
                    ffma2(a1A, W1d[j], d0); ffma2(a1B, W1d[j + 1], d1);
                }
                #pragma unroll 4
                for (int j = 0; j < 64; j += 2) {
                    ull c0 = cg2[j], c1 = cg2[j + 1];
                    ffma2(a0A, W0c[j], c0); ffma2(a0B, W0c[j + 1], c1);
                    ffma2(a1A, W1c[j], c0); ffma2(a1B, W1c[j + 1], c1);
                }
                float2 p = unpack2(a0A), q = unpack2(a0B);
                s_base[r * 64 + la] = (p.x + q.x) + (p.y + q.y);
                p = unpack2(a1A); q = unpack2(a1B);
                s_base[r * 64 + la + 32] = (p.x + q.x) + (p.y + q.y);
            }
            __syncwarp();
            // ---- D2+D3: temporal scores + softmax (warp) -> beta ----
            {
                const float* pp = g_proj + ((size_t)(b0 + r)) * ATT * Tt;
                const float* bg = s_base + r * 64;
                float ac0 = vd_b_r, ac1 = vd_b_r;
                #pragma unroll 4
                for (int a = 0; a < 64; ++a) {
                    float dca = bg[a];
                    float vw = s_vdw[a];
                    ac0 = fmaf(vw, tanh_fast(pp[a * 64 + la] + dca), ac0);
                    ac1 = fmaf(vw, tanh_fast(pp[a * 64 + la + 32] + dca), ac1);
                }
                float m = fmaxf(ac0, ac1);
                #pragma unroll
                for (int o = 16; o; o >>= 1) m = fmaxf(m, __shfl_xor_sync(0xffffffffu, m, o));
                float e0 = __expf(ac0 - m), e1 = __expf(ac1 - m);
                float ss = e0 + e1;
                #pragma unroll
                for (int o = 16; o; o >>= 1) ss += __shfl_xor_sync(0xffffffffu, ss, o);
                float inv = 1.f / ss;
                s_sc[r * 64 + la]      = e0 * inv;
                s_sc[r * 64 + la + 32] = e1 * inv;
            }
            __syncwarp();
            // ---- D4: context -> s_x (4 units/lane, float4) ----
            {
                const int u4 = 4 * la;
                const float4* hp4 = (const float4*)(g_hid + ((size_t)(b0 + r) * Tt) * Hh + u4);
                const float* be = s_sc + r * 64;
                float4 acc = make_float4(0.f, 0.f, 0.f, 0.f);
                #pragma unroll 4
                for (int tt = 0; tt < 64; ++tt) {
                    float b = be[tt];
                    float4 hv = hp4[tt * 32];
                    acc.x = fmaf(b, hv.x, acc.x);
                    acc.y = fmaf(b, hv.y, acc.y);
                    acc.z = fmaf(b, hv.z, acc.z);
                    acc.w = fmaf(b, hv.w, acc.w);
                }
                *(float4*)(s_x + r * 128 + u4) = acc;
            }
        } else {
            // ---- D5: Whh_dec · d -> s_gB, nondup acts ----
            gemm_nd<128>(WhhPd + gt, s_h, s_gB, gt);
        }
        __syncthreads();
        // ---- D6: LSTM update (gB + bias + dWih*y_prev) ----
        {
            const float2* gB2 = (const float2*)(s_gB + gU * 512);
            const float2* b2  = (const float2*)s_bias;
            const float2* w2p = (const float2*)s_dWih;
            const int h2i = i2 >> 1;
            float y = s_yprev[gU];
            float pre[4][2];
            #pragma unroll
            for (int q = 0; q < 4; ++q) {
                int idx = q * 64 + h2i;
                float2 vB = gB2[idx], vb = b2[idx], vw = w2p[idx];
                pre[q][0] = fmaf(vw.x, y, vB.x + vb.x);
                pre[q][1] = fmaf(vw.y, y, vB.y + vb.y);
            }
            #pragma unroll
            for (int j = 0; j < 2; ++j) {
                float ig = sigm(pre[0][j]);
                float fg = sigm(pre[1][j]);
                float gv = tanh_acc(pre[2][j]);
                float og = sigm(pre[3][j]);
                float c2 = fmaf(fg, s_c[gU * 128 + i2 + j], ig * gv);
                float h2 = og * tanh_acc(c2);
                s_c[gU * 128 + i2 + j] = c2;
                s_h[gU * 128 + i2 + j] = h2;
            }
        }
        __syncthreads();
    }
    // final output step
    if (wrp < 8) do_D7(HOR - 1);
}

extern "C" void kernel_launch(void* const* d_in, const int* in_sizes, int n_in,
                              void* d_out, int out_size) {
    const float* X        = (const float*)d_in[0];
    const float* y_hist   = (const float*)d_in[1];
    const float* We_w     = (const float*)d_in[2];
    const float* We_b     = (const float*)d_in[3];
    const float* ve_w     = (const float*)d_in[4];
    const float* ve_b     = (const float*)d_in[5];
    const float* enc_Wih  = (const float*)d_in[6];
    const float* enc_Whh  = (const float*)d_in[7];
    const float* enc_bih  = (const float*)d_in[8];
    const float* enc_bhh  = (const float*)d_in[9];
    const float* dec_Wih  = (const float*)d_in[10];
    const float* dec_Whh  = (const float*)d_in[11];
    const float* dec_bih  = (const float*)d_in[12];
    const float* dec_bhh  = (const float*)d_in[13];
    const float* Wd_w     = (const float*)d_in[14];
    const float* Wd_b     = (const float*)d_in[15];
    const float* vd_w     = (const float*)d_in[16];
    const float* vd_b     = (const float*)d_in[17];
    const float* fc_w     = (const float*)d_in[18];
    const float* fc_b     = (const float*)d_in[19];
    float* out = (float*)d_out;

    cudaFuncSetAttribute(darnn_kernel,
                         cudaFuncAttributeMaxDynamicSharedMemorySize, SMEM_BYTES);

    transpose_k<<<(512 * 128 + 255) / 256, 256>>>(enc_Wih, enc_Whh, dec_Whh);
    darnn_kernel<<<NCTAS, NTHR, SMEM_BYTES>>>(
        X, y_hist, We_w, We_b, ve_w, ve_b,
        enc_bih, enc_bhh, dec_Wih, dec_bih, dec_bhh,
        Wd_w, Wd_b, vd_w, vd_b, fc_w, fc_b, out);
}

// round 11
// speedup vs baseline: 1.2449x; 1.2449x over previous
#include <cuda_runtime.h>
#include <cstdint>

typedef unsigned long long ull;

#define Bsz 1024
#define Tt 64
#define Dd 128
#define Hh 128
#define ATT 64
#define HOR 24
#define G 8
#define NCTAS (Bsz/G)
#define NTHR 512

// named barriers (count = 512 always): producers bar.arrive, consumers bar.sync
#define BARX 1   // x_tilde ready   (att -> gemm)
#define BARG 2   // gates ready     (gemm -> att)
#define BARH 3   // h/hd ready      (att -> gemm)

// ---------------- device scratch ----------------
__device__ float g_WihT[Dd * 4 * Hh];   // [k][512o]
__device__ float g_WhhT[Hh * 4 * Hh];   // [k][512o]
__device__ float g_WhhTd[Hh * 4 * Hh];  // [k][512o]
__device__ float g_hid[(size_t)Bsz * Tt * Hh];   // [b][t][h]
__device__ float g_proj[(size_t)Bsz * ATT * Tt]; // [b][a][t]

// ---------------- helpers ----------------
__device__ __forceinline__ float tanh_fast(float x) {
    float y; asm("tanh.approx.f32 %0, %1;" : "=f"(y) : "f"(x)); return y;
}
__device__ __forceinline__ float sigm(float x) { return 1.f / (1.f + __expf(-x)); }
__device__ __forceinline__ float tanh_acc(float x) {
    float ax = fabsf(x);
    float e = __expf(-2.f * ax);
    float t = (1.f - e) / (1.f + e);
    return copysignf(t, x);
}
__device__ __forceinline__ ull pack2(float lo, float hi) {
    ull r; asm("mov.b64 %0, {%1,%2};" : "=l"(r) : "f"(lo), "f"(hi)); return r;
}
__device__ __forceinline__ float2 unpack2(ull v) {
    float2 r; asm("mov.b64 {%0,%1}, %2;" : "=f"(r.x), "=f"(r.y) : "l"(v)); return r;
}
__device__ __forceinline__ void ffma2(ull &d, ull a, ull b) {
    asm("fma.rn.f32x2 %0, %1, %2, %0;" : "+l"(d) : "l"(a), "l"(b));
}
__device__ __forceinline__ void bar_arrive(int id) {
    asm volatile("bar.arrive %0, 512;" :: "r"(id) : "memory");
}
__device__ __forceinline__ void bar_wait(int id) {
    asm volatile("bar.sync %0, 512;" :: "r"(id) : "memory");
}
__device__ __forceinline__ void barw(int id) {  // warpgroup barrier (128 thr)
    asm volatile("bar.sync %0, 128;" :: "r"(id) : "memory");
}

// ---- R6 gemm inner loop (dup acts), accumulate-only ----
// Wbase: weight ull array, k-th o-pair at Wbase[k*256] (pre-offset by o-pair)
// act:   duplicated activations, g-th row at act + g*256
template<int NK>
__device__ __forceinline__ void gemm_acc(const ull* __restrict__ Wbase,
                                         const float* __restrict__ act,
                                         ull* acc) {
    #pragma unroll 2
    for (int kp = 0; kp < NK / 2; ++kp) {
        ull w0 = Wbase[(2 * kp) * 256];
        ull w1 = Wbase[(2 * kp + 1) * 256];
        #pragma unroll
        for (int g = 0; g < 8; ++g) {
            ulonglong2 hp = *(const ulonglong2*)(act + g * 256 + 4 * kp);
            ffma2(acc[g], w0, hp.x);
            ffma2(acc[g], w1, hp.y);
        }
    }
}

// ---------------- prologue: transpose LSTM weights ----------------
__global__ void transpose_k(const float* __restrict__ Wih,
                            const float* __restrict__ Whh,
                            const float* __restrict__ Wdh) {
    int i = blockIdx.x * blockDim.x + threadIdx.x;
    if (i < 512 * 128) {
        int o = i >> 7, k = i & 127;
        g_WihT[k * 512 + o]  = Wih[i];
        g_WhhT[k * 512 + o]  = Whh[i];
        g_WhhTd[k * 512 + o] = Wdh[i];
    }
}

// smem float offsets (all multiples of 4)
#define OFF_W      0
#define SZ_W       24704              // 64*386 (enc stride 258, dec 386)
#define OFF_H      (OFF_W + SZ_W)
#define OFF_C      (OFF_H + 1024)
#define OFF_X      (OFF_C + 1024)     // context / proj staging
#define OFF_XD     (OFF_X + 1024)     // x_tilde duplicated [g][2k]
#define OFF_HD     (OFF_XD + 2048)    // h duplicated [g][2k]
#define OFF_BASE   (OFF_HD + 2048)
#define OFF_SC     (OFF_BASE + 512)
#define OFF_GATES  (OFF_SC + 512)     // complete gate preacts [g][512]
#define OFF_BIAS   (OFF_GATES + 4096)
#define OFF_WEB    (OFF_BIAS + 512)
#define OFF_WV     (OFF_WEB + 64)     // (w_feat, ve_w) pairs, 128 floats
#define OFF_WDB    (OFF_WV + 128)
#define OFF_VDW    (OFF_WDB + 64)
#define OFF_DWIH   (OFF_VDW + 64)
#define OFF_FCW    (OFF_DWIH + 512)
#define OFF_YH     (OFF_FCW + 320)
#define OFF_YPREV  (OFF_YH + 512)
#define SMEM_FLOATS (OFF_YPREV + 8)
#define SMEM_BYTES  (SMEM_FLOATS * 4)

__global__ void __launch_bounds__(NTHR, 1)
darnn_kernel(const float* __restrict__ X,        const float* __restrict__ y_hist,
             const float* __restrict__ We_w,     const float* __restrict__ We_b,
             const float* __restrict__ ve_w,     const float* __restrict__ ve_b,
             const float* __restrict__ enc_bih,  const float* __restrict__ enc_bhh,
             const float* __restrict__ dec_Wih,  const float* __restrict__ dec_bih,
             const float* __restrict__ dec_bhh,
             const float* __restrict__ Wd_w,     const float* __restrict__ Wd_b,
             const float* __restrict__ vd_w,     const float* __restrict__ vd_b,
             const float* __restrict__ fc_w,     const float* __restrict__ fc_b,
             float* __restrict__ out) {
    extern __shared__ float sm[];
    float* sW      = sm + OFF_W;
    float* s_h     = sm + OFF_H;
    float* s_c     = sm + OFF_C;
    float* s_x     = sm + OFF_X;
    float* s_xd    = sm + OFF_XD;
    float* s_hd    = sm + OFF_HD;
    float* s_base  = sm + OFF_BASE;
    float* s_sc    = sm + OFF_SC;
    float* s_gates = sm + OFF_GATES;
    float* s_bias  = sm + OFF_BIAS;
    float* s_Web   = sm + OFF_WEB;
    float* s_wv    = sm + OFF_WV;
    float* s_Wdb   = sm + OFF_WDB;
    float* s_vdw   = sm + OFF_VDW;
    float* s_dWih  = sm + OFF_DWIH;
    float* s_fcw   = sm + OFF_FCW;
    float* s_yh    = sm + OFF_YH;
    float* s_yprev = sm + OFF_YPREV;

    const int tid  = threadIdx.x;
    const int lane = tid & 31;
    const int wrp  = tid >> 5;
    const int la   = lane;
    const int b0   = blockIdx.x * G;
    const int op   = tid - 256;         // gemm-warp o-pair (warps 8-15)
    // proj-phase mapping
    const int gg   = tid >> 7;
    const int wt   = tid & 127;
    const int g0p  = gg * 2, g1p = g0p + 1;
    const int glp  = g0p + (wt >> 6);
    const int a63  = tid & 63;
    const int WB   = 4 + gg;            // ids 4..7 (avoid 1..3)

    const float ve_b_r = ve_b[0];

    // ---------- preload (encoder) ----------
    for (int i = tid; i < 64 * 257; i += NTHR) {
        int r = i / 257, c = i - r * 257;
        sW[r * 258 + c] = We_w[i];
    }
    if (tid < 512) s_bias[tid] = enc_bih[tid] + enc_bhh[tid];
    if (tid < 64) {
        s_Web[tid] = We_b[tid];
        ((float2*)s_wv)[tid] = make_float2(We_w[tid * 257 + 256], ve_w[tid]);
    }
    if (tid < G * Tt) s_yh[tid] = y_hist[b0 * Tt + tid];
    for (int i = tid; i < 1024; i += NTHR) { s_h[i] = 0.f; s_c[i] = 0.f; }
    for (int i = tid; i < 2048; i += NTHR) s_hd[i] = 0.f;
    __syncthreads();

    const ull* WihP  = reinterpret_cast<const ull*>(g_WihT);   // [k][256 o-pairs]
    const ull* WhhP  = reinterpret_cast<const ull*>(g_WhhT);
    const ull* WhhPd = reinterpret_cast<const ull*>(g_WhhTd);

    // ================= ENCODER: 64 steps =================
    if (wrp < 8) {
        const int r = wrp;   // batch row owned by this warp
        for (int t = 0; t < Tt; ++t) {
            // ---- E2: base[a] for a = la, la+32 ----
            {
                const ull* Wr0 = (const ull*)(sW + la * 258);
                const ull* Wr1 = (const ull*)(sW + (la + 32) * 258);
                const ull* hg2 = (const ull*)(s_h + r * 128);
                const ull* cg2 = (const ull*)(s_c + r * 128);
                ull a0A = pack2(s_Web[la], 0.f), a0B = 0ULL;
                ull a1A = pack2(s_Web[la + 32], 0.f), a1B = 0ULL;
                #pragma unroll 4
                for (int j = 0; j < 64; j += 2) {
                    ull h0 = hg2[j], h1 = hg2[j + 1];
                    ffma2(a0A, Wr0[j], h0); ffma2(a0B, Wr0[j + 1], h1);
                    ffma2(a1A, Wr1[j], h0); ffma2(a1B, Wr1[j + 1], h1);
                }
                #pragma unroll 4
                for (int j = 0; j < 64; j += 2) {
                    ull c0 = cg2[j], c1 = cg2[j + 1];
                    ffma2(a0A, Wr0[64 + j], c0); ffma2(a0B, Wr0[64 + j + 1], c1);
                    ffma2(a1A, Wr1[64 + j], c0); ffma2(a1B, Wr1[64 + j + 1], c1);
                }
                float2 p = unpack2(a0A), q = unpack2(a0B);
                s_base[r * 64 + la] = (p.x + q.x) + (p.y + q.y);
                p = unpack2(a1A); q = unpack2(a1B);
                s_base[r * 64 + la + 32] = (p.x + q.x) + (p.y + q.y);
            }
            __syncwarp();
            // ---- E3+E4: scores + softmax (warp) + x_tilde (dup) ----
            {
                const float* Xg = X + ((size_t)(b0 + r) * Tt + t) * Dd;
                float xv0 = Xg[la], xv1 = Xg[la + 32], xv2 = Xg[la + 64], xv3 = Xg[la + 96];
                float s0 = ve_b_r, s1 = ve_b_r, s2 = ve_b_r, s3 = ve_b_r;
                const float* bg = s_base + r * 64;
                const float2* wv = (const float2*)s_wv;
                #pragma unroll 8
                for (int a = 0; a < 64; ++a) {
                    float ba = bg[a];
                    float2 w = wv[a];   // (w_feat, ve_w)
                    s0 = fmaf(w.y, tanh_fast(fmaf(xv0, w.x, ba)), s0);
                    s1 = fmaf(w.y, tanh_fast(fmaf(xv1, w.x, ba)), s1);
                    s2 = fmaf(w.y, tanh_fast(fmaf(xv2, w.x, ba)), s2);
                    s3 = fmaf(w.y, tanh_fast(fmaf(xv3, w.x, ba)), s3);
                }
                float m = fmaxf(fmaxf(s0, s1), fmaxf(s2, s3));
                #pragma unroll
                for (int o = 16; o; o >>= 1) m = fmaxf(m, __shfl_xor_sync(0xffffffffu, m, o));
                float e0 = __expf(s0 - m), e1 = __expf(s1 - m);
                float e2 = __expf(s2 - m), e3 = __expf(s3 - m);
                float ss = (e0 + e1) + (e2 + e3);
                #pragma unroll
                for (int o = 16; o; o >>= 1) ss += __shfl_xor_sync(0xffffffffu, ss, o);
                float inv = 1.f / ss;
                float* xd = s_xd + r * 256;
                float v0 = xv0 * e0 * inv, v1 = xv1 * e1 * inv;
                float v2 = xv2 * e2 * inv, v3 = xv3 * e3 * inv;
                *(float2*)(xd + 2 * la)       = make_float2(v0, v0);
                *(float2*)(xd + 2 * la + 64)  = make_float2(v1, v1);
                *(float2*)(xd + 2 * la + 128) = make_float2(v2, v2);
                *(float2*)(xd + 2 * la + 192) = make_float2(v3, v3);
            }
            bar_arrive(BARX);       // x_tilde ready for gemm warps
            bar_wait(BARG);         // wait for complete gates
            // ---- update: warp r handles its own 128 units, 4 per lane ----
            {
                const int ul = lane * 4;
                const float* gr = s_gates + r * 512;
                float4 gI = *(const float4*)(gr + ul);
                float4 gF = *(const float4*)(gr + 128 + ul);
                float4 gG = *(const float4*)(gr + 256 + ul);
                float4 gO = *(const float4*)(gr + 384 + ul);
                float4 co = *(const float4*)(s_c + r * 128 + ul);
                float I[4] = {gI.x, gI.y, gI.z, gI.w};
                float F[4] = {gF.x, gF.y, gF.z, gF.w};
                float Gv[4] = {gG.x, gG.y, gG.z, gG.w};
                float O[4] = {gO.x, gO.y, gO.z, gO.w};
                float C[4] = {co.x, co.y, co.z, co.w};
                float hh[4], cc[4];
                #pragma unroll
                for (int j = 0; j < 4; ++j) {
                    float ig = sigm(I[j]);
                    float fg = sigm(F[j]);
                    float gv = tanh_acc(Gv[j]);
                    float og = sigm(O[j]);
                    cc[j] = fmaf(fg, C[j], ig * gv);
                    hh[j] = og * tanh_acc(cc[j]);
                }
                *(float4*)(s_c + r * 128 + ul) = make_float4(cc[0], cc[1], cc[2], cc[3]);
                *(float4*)(s_h + r * 128 + ul) = make_float4(hh[0], hh[1], hh[2], hh[3]);
                *(float4*)(s_hd + r * 256 + 2 * ul)     = make_float4(hh[0], hh[0], hh[1], hh[1]);
                *(float4*)(s_hd + r * 256 + 2 * ul + 4) = make_float4(hh[2], hh[2], hh[3], hh[3]);
                *(float4*)(g_hid + ((size_t)(b0 + r) * Tt + t) * Hh + ul) =
                    make_float4(hh[0], hh[1], hh[2], hh[3]);
            }
            bar_arrive(BARH);       // h ready for next step's Whh
        }
    } else {
        // gemm warps: full gate GEMM (bias + Whh·h + Wih·x_tilde), single write
        const ull bias2 = pack2(s_bias[2 * op], s_bias[2 * op + 1]);
        for (int t = 0; t < Tt; ++t) {
            if (t > 0) bar_wait(BARH);
            ull acc[8];
            #pragma unroll
            for (int g = 0; g < 8; ++g) acc[g] = bias2;
            gemm_acc<128>(WhhP + op, s_hd, acc);
            bar_wait(BARX);
            gemm_acc<128>(WihP + op, s_xd, acc);
            #pragma unroll
            for (int g = 0; g < 8; ++g) {
                float2 r2 = unpack2(acc[g]);
                *(float2*)(s_gates + g * 512 + 2 * op) = r2;
            }
            bar_arrive(BARG);
        }
        bar_wait(BARH);   // drain att's final arrive (t = Tt-1)
    }
    __syncthreads();

    // ================= enc_proj =================
    for (int i = tid; i < 64 * 384; i += NTHR) {
        int r = i / 384, c = i - r * 384;
        sW[r * 386 + c] = Wd_w[i];
    }
    __syncthreads();
    for (int t = 0; t < Tt; ++t) {
        s_x[g0p * 128 + wt] = g_hid[((size_t)(b0 + g0p) * Tt + t) * Hh + wt];
        s_x[g1p * 128 + wt] = g_hid[((size_t)(b0 + g1p) * Tt + t) * Hh + wt];
        barw(WB);
        {
            const ull* Wr2 = (const ull*)(sW + a63 * 386);
            const ull* hg2 = (const ull*)(s_x + glp * 128);
            ull aA = 0ULL, aB = 0ULL;
            #pragma unroll 8
            for (int j = 0; j < 64; j += 2) {
                ffma2(aA, Wr2[j], hg2[j]);
                ffma2(aB, Wr2[j + 1], hg2[j + 1]);
            }
            float2 ra = unpack2(aA), rb = unpack2(aB);
            g_proj[((size_t)(b0 + glp)) * ATT * Tt + a63 * Tt + t] = (ra.x + rb.x) + (ra.y + rb.y);
        }
        barw(WB);
    }

    // ---------- preload (decoder) ----------
    __syncthreads();
    if (tid < 512) {
        s_bias[tid] = dec_bih[tid] + dec_bhh[tid];
        s_dWih[tid] = dec_Wih[tid];
    }
    if (tid < 64) { s_Wdb[tid] = Wd_b[tid]; s_vdw[tid] = vd_w[tid]; }
    if (tid < 320) s_fcw[tid] = fc_w[tid];
    for (int i = tid; i < 1024; i += NTHR) { s_h[i] = 0.f; s_c[i] = 0.f; }
    for (int i = tid; i < 2048; i += NTHR) s_hd[i] = 0.f;
    if (tid < G) s_yprev[tid] = s_yh[tid * Tt + Tt - 1];
    const float vd_b_r = vd_b[0];
    const float fc_b_r = fc_b[0];
    __syncthreads();

    // ================= DECODER: 24 steps =================
    if (wrp < 8) {
        const int r = wrp;
        auto do_D7 = [&](int s) {
            float acc = 0.f;
            #pragma unroll
            for (int it = 0; it < 10; ++it) {
                int idx = lane + it * 32;
                float v;
                if (idx < 128)      v = s_h[r * 128 + idx];
                else if (idx < 256) v = s_x[r * 128 + idx - 128];
                else                v = s_yh[r * 64 + idx - 256];
                acc = fmaf(s_fcw[idx], v, acc);
            }
            #pragma unroll
            for (int o = 16; o; o >>= 1) acc += __shfl_xor_sync(0xffffffffu, acc, o);
            if (lane == 0) {
                float ov = acc + fc_b_r;
                s_yprev[r] = ov;
                out[(b0 + r) * HOR + s] = ov;
            }
        };
        for (int s = 0; s < HOR; ++s) {
            if (s > 0) do_D7(s - 1);
            // ---- D1: dc[a] for a = la, la+32 ----
            {
                const ull* W0d = (const ull*)(sW + la * 386 + 128);
                const ull* W0c = (const ull*)(sW + la * 386 + 256);
                const ull* W1d = (const ull*)(sW + (la + 32) * 386 + 128);
                const ull* W1c = (const ull*)(sW + (la + 32) * 386 + 256);
                const ull* dg2 = (const ull*)(s_h + r * 128);
                const ull* cg2 = (const ull*)(s_c + r * 128);
                ull a0A = pack2(s_Wdb[la], 0.f), a0B = 0ULL;
                ull a1A = pack2(s_Wdb[la + 32], 0.f), a1B = 0ULL;
                #pragma unroll 4
                for (int j = 0; j < 64; j += 2) {
                    ull d0 = dg2[j], d1 = dg2[j + 1];
                    ffma2(a0A, W0d[j], d0); ffma2(a0B, W0d[j + 1], d1);
                    ffma2(a1A, W1d[j], d0); ffma2(a1B, W1d[j + 1], d1);
                }
                #pragma unroll 4
                for (int j = 0; j < 64; j += 2) {
                    ull c0 = cg2[j], c1 = cg2[j + 1];
                    ffma2(a0A, W0c[j], c0); ffma2(a0B, W0c[j + 1], c1);
                    ffma2(a1A, W1c[j], c0); ffma2(a1B, W1c[j + 1], c1);
                }
                float2 p = unpack2(a0A), q = unpack2(a0B);
                s_base[r * 64 + la] = (p.x + q.x) + (p.y + q.y);
                p = unpack2(a1A); q = unpack2(a1B);
                s_base[r * 64 + la + 32] = (p.x + q.x) + (p.y + q.y);
            }
            __syncwarp();
            // ---- D2+D3: temporal scores + softmax -> beta ----
            {
                const float* pp = g_proj + ((size_t)(b0 + r)) * ATT * Tt;
                const float* bg = s_base + r * 64;
                float ac0 = vd_b_r, ac1 = vd_b_r;
                #pragma unroll 4
                for (int a = 0; a < 64; ++a) {
                    float dca = bg[a];
                    float vw = s_vdw[a];
                    ac0 = fmaf(vw, tanh_fast(pp[a * 64 + la] + dca), ac0);
                    ac1 = fmaf(vw, tanh_fast(pp[a * 64 + la + 32] + dca), ac1);
                }
                float m = fmaxf(ac0, ac1);
                #pragma unroll
                for (int o = 16; o; o >>= 1) m = fmaxf(m, __shfl_xor_sync(0xffffffffu, m, o));
                float e0 = __expf(ac0 - m), e1 = __expf(ac1 - m);
                float ss = e0 + e1;
                #pragma unroll
                for (int o = 16; o; o >>= 1) ss += __shfl_xor_sync(0xffffffffu, ss, o);
                float inv = 1.f / ss;
                s_sc[r * 64 + la]      = e0 * inv;
                s_sc[r * 64 + la + 32] = e1 * inv;
            }
            __syncwarp();
            // ---- D4: context -> s_x (4 units/lane) ----
            {
                const int u4 = 4 * la;
                const float4* hp4 = (const float4*)(g_hid + ((size_t)(b0 + r) * Tt) * Hh + u4);
                const float* be = s_sc + r * 64;
                float4 acc = make_float4(0.f, 0.f, 0.f, 0.f);
                #pragma unroll 4
                for (int tt = 0; tt < 64; ++tt) {
                    float b = be[tt];
                    float4 hv = hp4[tt * 32];
                    acc.x = fmaf(b, hv.x, acc.x);
                    acc.y = fmaf(b, hv.y, acc.y);
                    acc.z = fmaf(b, hv.z, acc.z);
                    acc.w = fmaf(b, hv.w, acc.w);
                }
                *(float4*)(s_x + r * 128 + u4) = acc;
            }
            bar_wait(BARG);     // wait decoder gates
            // ---- update: warp r, 4 units/lane, + dWih*y ----
            {
                const int ul = lane * 4;
                const float* gr = s_gates + r * 512;
                float y = s_yprev[r];
                float4 gI = *(const float4*)(gr + ul);
                float4 gF = *(const float4*)(gr + 128 + ul);
                float4 gG = *(const float4*)(gr + 256 + ul);
                float4 gO = *(const float4*)(gr + 384 + ul);
                float4 wI = *(const float4*)(s_dWih + ul);
                float4 wF = *(const float4*)(s_dWih + 128 + ul);
                float4 wG = *(const float4*)(s_dWih + 256 + ul);
                float4 wO = *(const float4*)(s_dWih + 384 + ul);
                float4 co = *(const float4*)(s_c + r * 128 + ul);
                float I[4] = {fmaf(wI.x, y, gI.x), fmaf(wI.y, y, gI.y), fmaf(wI.z, y, gI.z), fmaf(wI.w, y, gI.w)};
                float F[4] = {fmaf(wF.x, y, gF.x), fmaf(wF.y, y, gF.y), fmaf(wF.z, y, gF.z), fmaf(wF.w, y, gF.w)};
                float Gv[4] = {fmaf(wG.x, y, gG.x), fmaf(wG.y, y, gG.y), fmaf(wG.z, y, gG.z), fmaf(wG.w, y, gG.w)};
                float O[4] = {fmaf(wO.x, y, gO.x), fmaf(wO.y, y, gO.y), fmaf(wO.z, y, gO.z), fmaf(wO.w, y, gO.w)};
                float C[4] = {co.x, co.y, co.z, co.w};
                float hh[4], cc[4];
                #pragma unroll
                for (int j = 0; j < 4; ++j) {
                    float ig = sigm(I[j]);
                    float fg = sigm(F[j]);
                    float gv = tanh_acc(Gv[j]);
                    float og = sigm(O[j]);
                    cc[j] = fmaf(fg, C[j], ig * gv);
                    hh[j] = og * tanh_acc(cc[j]);
                }
                *(float4*)(s_c + r * 128 + ul) = make_float4(cc[0], cc[1], cc[2], cc[3]);
                *(float4*)(s_h + r * 128 + ul) = make_float4(hh[0], hh[1], hh[2], hh[3]);
                *(float4*)(s_hd + r * 256 + 2 * ul)     = make_float4(hh[0], hh[0], hh[1], hh[1]);
                *(float4*)(s_hd + r * 256 + 2 * ul + 4) = make_float4(hh[2], hh[2], hh[3], hh[3]);
            }
            if (s + 1 < HOR) bar_arrive(BARH);
        }
        do_D7(HOR - 1);
    } else {
        const ull bias2d = pack2(s_bias[2 * op], s_bias[2 * op + 1]);
        for (int s = 0; s < HOR; ++s) {
            if (s > 0) bar_wait(BARH);
            ull acc[8];
            #pragma unroll
            for (int g = 0; g < 8; ++g) acc[g] = bias2d;
            gemm_acc<128>(WhhPd + op, s_hd, acc);
            #pragma unroll
            for (int g = 0; g < 8; ++g) {
                float2 r2 = unpack2(acc[g]);
                *(float2*)(s_gates + g * 512 + 2 * op) = r2;
            }
            bar_arrive(BARG);
        }
    }
}

extern "C" void kernel_launch(void* const* d_in, const int* in_sizes, int n_in,
                              void* d_out, int out_size) {
    const float* X        = (const float*)d_in[0];
    const float* y_hist   = (const float*)d_in[1];
    const float* We_w     = (const float*)d_in[2];
    const float* We_b     = (const float*)d_in[3];
    const float* ve_w     = (const float*)d_in[4];
    const float* ve_b     = (const float*)d_in[5];
    const float* enc_Wih  = (const float*)d_in[6];
    const float* enc_Whh  = (const float*)d_in[7];
    const float* enc_bih  = (const float*)d_in[8];
    const float* enc_bhh  = (const float*)d_in[9];
    const float* dec_Wih  = (const float*)d_in[10];
    const float* dec_Whh  = (const float*)d_in[11];
    const float* dec_bih  = (const float*)d_in[12];
    const float* dec_bhh  = (const float*)d_in[13];
    const float* Wd_w     = (const float*)d_in[14];
    const float* Wd_b     = (const float*)d_in[15];
    const float* vd_w     = (const float*)d_in[16];
    const float* vd_b     = (const float*)d_in[17];
    const float* fc_w     = (const float*)d_in[18];
    const float* fc_b     = (const float*)d_in[19];
    float* out = (float*)d_out;

    cudaFuncSetAttribute(darnn_kernel,
                         cudaFuncAttributeMaxDynamicSharedMemorySize, SMEM_BYTES);

    transpose_k<<<(512 * 128 + 255) / 256, 256>>>(enc_Wih, enc_Whh, dec_Whh);
    darnn_kernel<<<NCTAS, NTHR, SMEM_BYTES>>>(
        X, y_hist, We_w, We_b, ve_w, ve_b,
        enc_bih, enc_bhh, dec_Wih, dec_bih, dec_bhh,
        Wd_w, Wd_b, vd_w, vd_b, fc_w, fc_b, out);
}

// round 12
// speedup vs baseline: 1.4784x; 1.1876x over previous
#include <cuda_runtime.h>
#include <cstdint>

typedef unsigned long long ull;

#define Bsz 1024
#define Tt 64
#define Dd 128
#define Hh 128
#define ATT 64
#define HOR 24
#define NTHR 512
#define NC7 136          // CTAs with 7 rows
#define NCTAS 148        // 136*7 + 12*6 = 1024

// ---------------- device scratch ----------------
__device__ float g_WihT[Dd * 4 * Hh];   // [k][512o]
__device__ float g_WhhT[Hh * 4 * Hh];   // [k][512o]
__device__ float g_WhhTd[Hh * 4 * Hh];  // [k][512o]
__device__ float g_hid[(size_t)Bsz * Tt * Hh];   // [b][t][h]
__device__ float g_proj[(size_t)Bsz * ATT * Tt]; // [b][a][t]

// ---------------- helpers ----------------
__device__ __forceinline__ float tanh_fast(float x) {
    float y; asm("tanh.approx.f32 %0, %1;" : "=f"(y) : "f"(x)); return y;
}
__device__ __forceinline__ float sigm(float x) { return 1.f / (1.f + __expf(-x)); }
__device__ __forceinline__ float tanh_acc(float x) {
    float ax = fabsf(x);
    float e = __expf(-2.f * ax);
    float t = (1.f - e) / (1.f + e);
    return copysignf(t, x);
}
__device__ __forceinline__ ull pack2(float lo, float hi) {
    ull r; asm("mov.b64 %0, {%1,%2};" : "=l"(r) : "f"(lo), "f"(hi)); return r;
}
__device__ __forceinline__ float2 unpack2(ull v) {
    float2 r; asm("mov.b64 {%0,%1}, %2;" : "=f"(r.x), "=f"(r.y) : "l"(v)); return r;
}
__device__ __forceinline__ void ffma2(ull &d, ull a, ull b) {
    asm("fma.rn.f32x2 %0, %1, %2, %0;" : "+l"(d) : "l"(a), "l"(b));
}
__device__ __forceinline__ void barw(int id) {  // warpgroup barrier (128 thr)
    asm volatile("bar.sync %0, 128;" :: "r"(id) : "memory");
}

// ---------------- prologue: transpose LSTM weights ----------------
__global__ void transpose_k(const float* __restrict__ Wih,
                            const float* __restrict__ Whh,
                            const float* __restrict__ Wdh) {
    int i = blockIdx.x * blockDim.x + threadIdx.x;
    if (i < 512 * 128) {
        int o = i >> 7, k = i & 127;
        g_WihT[k * 512 + o]  = Wih[i];
        g_WhhT[k * 512 + o]  = Whh[i];
        g_WhhTd[k * 512 + o] = Wdh[i];
    }
}

// smem float offsets (all multiples of 4)
#define OFF_W      0
#define SZ_W       24704              // 64*386 (enc stride 258, dec 386)
#define OFF_H      (OFF_W + SZ_W)
#define OFF_C      (OFF_H + 1024)
#define OFF_X      (OFF_C + 1024)     // context / proj staging
#define OFF_XD     (OFF_X + 1024)     // x_tilde duplicated [g][2k]
#define OFF_HD     (OFF_XD + 2048)    // h duplicated [g][2k]
#define OFF_BASE   (OFF_HD + 2048)
#define OFF_SC     (OFF_BASE + 512)
#define OFF_GA     (OFF_SC + 512)     // Wih partial kh=0
#define OFF_GB     (OFF_GA + 4096)    // Whh full
#define OFF_GC     (OFF_GB + 4096)    // Wih partial kh=1
#define OFF_BIAS   (OFF_GC + 4096)
#define OFF_WEB    (OFF_BIAS + 512)
#define OFF_WV     (OFF_WEB + 64)     // (w_feat, ve_w) pairs, 128 floats
#define OFF_WDB    (OFF_WV + 128)
#define OFF_VDW    (OFF_WDB + 64)
#define OFF_DWIH   (OFF_VDW + 64)
#define OFF_FCW    (OFF_DWIH + 512)
#define OFF_YH     (OFF_FCW + 320)
#define OFF_YPREV  (OFF_YH + 512)
#define SMEM_FLOATS (OFF_YPREV + 8)
#define SMEM_BYTES  (SMEM_FLOATS * 4)

template<int GN>
__device__ __forceinline__ void darnn_body(
    const int b0,
    const float* __restrict__ X,        const float* __restrict__ y_hist,
    const float* __restrict__ We_w,     const float* __restrict__ We_b,
    const float* __restrict__ ve_w,     const float* __restrict__ ve_b,
    const float* __restrict__ enc_bih,  const float* __restrict__ enc_bhh,
    const float* __restrict__ dec_Wih,  const float* __restrict__ dec_bih,
    const float* __restrict__ dec_bhh,
    const float* __restrict__ Wd_w,     const float* __restrict__ Wd_b,
    const float* __restrict__ vd_w,     const float* __restrict__ vd_b,
    const float* __restrict__ fc_w,     const float* __restrict__ fc_b,
    float* __restrict__ out, float* sm)
{
    float* sW      = sm + OFF_W;
    float* s_h     = sm + OFF_H;
    float* s_c     = sm + OFF_C;
    float* s_x     = sm + OFF_X;
    float* s_xd    = sm + OFF_XD;
    float* s_hd    = sm + OFF_HD;
    float* s_base  = sm + OFF_BASE;
    float* s_sc    = sm + OFF_SC;
    float* s_gA    = sm + OFF_GA;
    float* s_gB    = sm + OFF_GB;
    float* s_gC    = sm + OFF_GC;
    float* s_bias  = sm + OFF_BIAS;
    float* s_Web   = sm + OFF_WEB;
    float* s_wv    = sm + OFF_WV;
    float* s_Wdb   = sm + OFF_WDB;
    float* s_vdw   = sm + OFF_VDW;
    float* s_dWih  = sm + OFF_DWIH;
    float* s_fcw   = sm + OFF_FCW;
    float* s_yh    = sm + OFF_YH;
    float* s_yprev = sm + OFF_YPREV;

    const int tid  = threadIdx.x;
    const int lane = tid & 31;
    const int wrp  = tid >> 5;
    const int la   = lane;
    const int gt   = tid - 256;         // gemm-warp thread id (warps 8-15)
    const int op4  = tid & 255;         // Wih-phase o-pair
    const int kh4  = tid >> 8;          // Wih-phase k-half
    const int gU   = tid >> 6;          // update: batch row
    const int i2   = (tid & 63) * 2;    // update: unit pair
    const int gg   = tid >> 7;          // proj-phase warpgroup
    const int wt   = tid & 127;
    const int g0p  = gg * 2, g1p = g0p + 1;
    const int glp  = g0p + (wt >> 6);
    const int a63  = tid & 63;
    const int WB   = 1 + gg;

    const float ve_b_r = ve_b[0];

    // ---------- preload (encoder) ----------
    for (int i = tid; i < 64 * 257; i += NTHR) {
        int r = i / 257, c = i - r * 257;
        sW[r * 258 + c] = We_w[i];
    }
    if (tid < 512) s_bias[tid] = enc_bih[tid] + enc_bhh[tid];
    if (tid < 64) {
        s_Web[tid] = We_b[tid];
        ((float2*)s_wv)[tid] = make_float2(We_w[tid * 257 + 256], ve_w[tid]);
    }
    if (tid < GN * Tt) s_yh[tid] = y_hist[b0 * Tt + tid];
    for (int i = tid; i < 1024; i += NTHR) { s_h[i] = 0.f; s_c[i] = 0.f; }
    for (int i = tid; i < 2048; i += NTHR) s_hd[i] = 0.f;
    __syncthreads();

    const ull* WihP  = reinterpret_cast<const ull*>(g_WihT);   // [k][256 o-pairs]
    const ull* WhhP  = reinterpret_cast<const ull*>(g_WhhT);
    const ull* WhhPd = reinterpret_cast<const ull*>(g_WhhTd);

    // ================= ENCODER: 64 steps =================
    for (int t = 0; t < Tt; ++t) {
        if (wrp < GN) {
            const int r = wrp;   // batch row
            // ---- E2: base[a] for a = la, la+32 ----
            {
                const ull* Wr0 = (const ull*)(sW + la * 258);
                const ull* Wr1 = (const ull*)(sW + (la + 32) * 258);
                const ull* hg2 = (const ull*)(s_h + r * 128);
                const ull* cg2 = (const ull*)(s_c + r * 128);
                ull a0A = pack2(s_Web[la], 0.f), a0B = 0ULL;
                ull a1A = pack2(s_Web[la + 32], 0.f), a1B = 0ULL;
                #pragma unroll 4
                for (int j = 0; j < 64; j += 2) {
                    ull h0 = hg2[j], h1 = hg2[j + 1];
                    ffma2(a0A, Wr0[j], h0); ffma2(a0B, Wr0[j + 1], h1);
                    ffma2(a1A, Wr1[j], h0); ffma2(a1B, Wr1[j + 1], h1);
                }
                #pragma unroll 4
                for (int j = 0; j < 64; j += 2) {
                    ull c0 = cg2[j], c1 = cg2[j + 1];
                    ffma2(a0A, Wr0[64 + j], c0); ffma2(a0B, Wr0[64 + j + 1], c1);
                    ffma2(a1A, Wr1[64 + j], c0); ffma2(a1B, Wr1[64 + j + 1], c1);
                }
                float2 p = unpack2(a0A), q = unpack2(a0B);
                s_base[r * 64 + la] = (p.x + q.x) + (p.y + q.y);
                p = unpack2(a1A); q = unpack2(a1B);
                s_base[r * 64 + la + 32] = (p.x + q.x) + (p.y + q.y);
            }
            __syncwarp();
            // ---- E3+E4: scores + softmax (warp) + x_tilde ----
            {
                const float* Xg = X + ((size_t)(b0 + r) * Tt + t) * Dd;
                float xv0 = Xg[la], xv1 = Xg[la + 32], xv2 = Xg[la + 64], xv3 = Xg[la + 96];
                float s0 = ve_b_r, s1 = ve_b_r, s2 = ve_b_r, s3 = ve_b_r;
                const float* bg = s_base + r * 64;
                const float2* wv = (const float2*)s_wv;
                #pragma unroll 8
                for (int a = 0; a < 64; ++a) {
                    float ba = bg[a];
                    float2 w = wv[a];   // (w_feat, ve_w)
                    s0 = fmaf(w.y, tanh_fast(fmaf(xv0, w.x, ba)), s0);
                    s1 = fmaf(w.y, tanh_fast(fmaf(xv1, w.x, ba)), s1);
                    s2 = fmaf(w.y, tanh_fast(fmaf(xv2, w.x, ba)), s2);
                    s3 = fmaf(w.y, tanh_fast(fmaf(xv3, w.x, ba)), s3);
                }
                float m = fmaxf(fmaxf(s0, s1), fmaxf(s2, s3));
                #pragma unroll
                for (int o = 16; o; o >>= 1) m = fmaxf(m, __shfl_xor_sync(0xffffffffu, m, o));
                float e0 = __expf(s0 - m), e1 = __expf(s1 - m);
                float e2 = __expf(s2 - m), e3 = __expf(s3 - m);
                float ss = (e0 + e1) + (e2 + e3);
                #pragma unroll
                for (int o = 16; o; o >>= 1) ss += __shfl_xor_sync(0xffffffffu, ss, o);
                float inv = 1.f / ss;
                float v0 = xv0 * e0 * inv, v1 = xv1 * e1 * inv;
                float v2 = xv2 * e2 * inv, v3 = xv3 * e3 * inv;
                float* xd = s_xd + r * 256;
                *(float2*)(xd + 2 * la)        = make_float2(v0, v0);
                *(float2*)(xd + 2 * la + 64)   = make_float2(v1, v1);
                *(float2*)(xd + 2 * la + 128)  = make_float2(v2, v2);
                *(float2*)(xd + 2 * la + 192)  = make_float2(v3, v3);
            }
        } else if (wrp >= 8) {
            // ---- Whh · h -> s_gB (full k=128), 256 threads, op = gt ----
            ull acc[GN];
            #pragma unroll
            for (int g = 0; g < GN; ++g) acc[g] = 0ULL;
            #pragma unroll 2
            for (int kp = 0; kp < 64; ++kp) {
                ull w0 = WhhP[(2 * kp) * 256 + gt];
                ull w1 = WhhP[(2 * kp + 1) * 256 + gt];
                #pragma unroll
                for (int g = 0; g < GN; ++g) {
                    ulonglong2 hp = *(const ulonglong2*)(s_hd + g * 256 + 4 * kp);
                    ffma2(acc[g], w0, hp.x);
                    ffma2(acc[g], w1, hp.y);
                }
            }
            #pragma unroll
            for (int g = 0; g < GN; ++g) {
                float2 r2 = unpack2(acc[g]);
                *(float2*)(s_gB + g * 512 + 2 * gt) = r2;
            }
        }
        __syncthreads();
        // ---- phase4: Wih · x_tilde, (op4, kh4) split ----
        {
            float* dst = kh4 ? s_gC : s_gA;
            const int kb = kh4 * 64;
            ull acc[GN];
            #pragma unroll
            for (int g = 0; g < GN; ++g) acc[g] = 0ULL;
            #pragma unroll 2
            for (int kp = 0; kp < 32; ++kp) {
                int k = kb + 2 * kp;
                ull w0 = WihP[k * 256 + op4];
                ull w1 = WihP[(k + 1) * 256 + op4];
                #pragma unroll
                for (int g = 0; g < GN; ++g) {
                    ulonglong2 xp = *(const ulonglong2*)(s_xd + g * 256 + 2 * k);
                    ffma2(acc[g], w0, xp.x);
                    ffma2(acc[g], w1, xp.y);
                }
            }
            #pragma unroll
            for (int g = 0; g < GN; ++g) {
                float2 r2 = unpack2(acc[g]);
                *(float2*)(dst + g * 512 + 2 * op4) = r2;
            }
        }
        __syncthreads();
        // ---- E6: LSTM update, 2 units per thread ----
        if (gU < GN) {
            const float2* gA2 = (const float2*)(s_gA + gU * 512);
            const float2* gB2 = (const float2*)(s_gB + gU * 512);
            const float2* gC2 = (const float2*)(s_gC + gU * 512);
            const float2* b2  = (const float2*)s_bias;
            const int h2i = i2 >> 1;
            float pre[4][2];
            #pragma unroll
            for (int q = 0; q < 4; ++q) {
                int idx = q * 64 + h2i;
                float2 vA = gA2[idx], vB = gB2[idx], vC = gC2[idx], vb = b2[idx];
                pre[q][0] = ((vA.x + vB.x) + (vC.x + vb.x));
                pre[q][1] = ((vA.y + vB.y) + (vC.y + vb.y));
            }
            float hh[2];
            #pragma unroll
            for (int j = 0; j < 2; ++j) {
                float ig = sigm(pre[0][j]);
                float fg = sigm(pre[1][j]);
                float gv = tanh_acc(pre[2][j]);
                float og = sigm(pre[3][j]);
                float c2 = fmaf(fg, s_c[gU * 128 + i2 + j], ig * gv);
                float h2 = og * tanh_acc(c2);
                s_c[gU * 128 + i2 + j] = c2;
                s_h[gU * 128 + i2 + j] = h2;
                hh[j] = h2;
            }
            *(float4*)(s_hd + gU * 256 + 2 * i2) = make_float4(hh[0], hh[0], hh[1], hh[1]);
            *(float2*)(g_hid + ((size_t)(b0 + gU) * Tt + t) * Hh + i2) = make_float2(hh[0], hh[1]);
        }
        __syncthreads();
    }

    // ================= enc_proj =================
    for (int i = tid; i < 64 * 384; i += NTHR) {
        int r = i / 384, c = i - r * 384;
        sW[r * 386 + c] = Wd_w[i];
    }
    __syncthreads();
    for (int t = 0; t < Tt; ++t) {
        if (g0p < GN) s_x[g0p * 128 + wt] = g_hid[((size_t)(b0 + g0p) * Tt + t) * Hh + wt];
        if (g1p < GN) s_x[g1p * 128 + wt] = g_hid[((size_t)(b0 + g1p) * Tt + t) * Hh + wt];
        barw(WB);
        if (glp < GN) {
            const ull* Wr2 = (const ull*)(sW + a63 * 386);
            const ull* hg2 = (const ull*)(s_x + glp * 128);
            ull aA = 0ULL, aB = 0ULL;
            #pragma unroll 8
            for (int j = 0; j < 64; j += 2) {
                ffma2(aA, Wr2[j], hg2[j]);
                ffma2(aB, Wr2[j + 1], hg2[j + 1]);
            }
            float2 ra = unpack2(aA), rb = unpack2(aB);
            g_proj[((size_t)(b0 + glp)) * ATT * Tt + a63 * Tt + t] = (ra.x + rb.x) + (ra.y + rb.y);
        }
        barw(WB);
    }

    // ---------- preload (decoder) ----------
    __syncthreads();
    if (tid < 512) {
        s_bias[tid] = dec_bih[tid] + dec_bhh[tid];
        s_dWih[tid] = dec_Wih[tid];
    }
    if (tid < 64) { s_Wdb[tid] = Wd_b[tid]; s_vdw[tid] = vd_w[tid]; }
    if (tid < 320) s_fcw[tid] = fc_w[tid];
    for (int i = tid; i < 1024; i += NTHR) { s_h[i] = 0.f; s_c[i] = 0.f; }
    for (int i = tid; i < 2048; i += NTHR) s_hd[i] = 0.f;
    if (tid < GN) s_yprev[tid] = s_yh[tid * Tt + Tt - 1];
    const float vd_b_r = vd_b[0];
    const float fc_b_r = fc_b[0];
    __syncthreads();

    // D7 helper
    auto do_D7 = [&](int s) {
        const int r = wrp;
        float acc = 0.f;
        #pragma unroll
        for (int it = 0; it < 10; ++it) {
            int idx = lane + it * 32;
            float v;
            if (idx < 128)      v = s_h[r * 128 + idx];
            else if (idx < 256) v = s_x[r * 128 + idx - 128];
            else                v = s_yh[r * 64 + idx - 256];
            acc = fmaf(s_fcw[idx], v, acc);
        }
        #pragma unroll
        for (int o = 16; o; o >>= 1) acc += __shfl_xor_sync(0xffffffffu, acc, o);
        if (lane == 0) {
            float ov = acc + fc_b_r;
            s_yprev[r] = ov;
            out[(b0 + r) * HOR + s] = ov;
        }
    };

    // ================= DECODER: 24 steps =================
    for (int s = 0; s < HOR; ++s) {
        if (wrp < GN) {
            const int r = wrp;
            if (s > 0) do_D7(s - 1);
            // ---- D1: dc[a] for a = la, la+32 ----
            {
                const ull* W0d = (const ull*)(sW + la * 386 + 128);
                const ull* W0c = (const ull*)(sW + la * 386 + 256);
                const ull* W1d = (const ull*)(sW + (la + 32) * 386 + 128);
                const ull* W1c = (const ull*)(sW + (la + 32) * 386 + 256);
                const ull* dg2 = (const ull*)(s_h + r * 128);
                const ull* cg2 = (const ull*)(s_c + r * 128);
                ull a0A = pack2(s_Wdb[la], 0.f), a0B = 0ULL;
                ull a1A = pack2(s_Wdb[la + 32], 0.f), a1B = 0ULL;
                #pragma unroll 4
                for (int j = 0; j < 64; j += 2) {
                    ull d0 = dg2[j], d1 = dg2[j + 1];
                    ffma2(a0A, W0d[j], d0); ffma2(a0B, W0d[j + 1], d1);
                    ffma2(a1A, W1d[j], d0); ffma2(a1B, W1d[j + 1], d1);
                }
                #pragma unroll 4
                for (int j = 0; j < 64; j += 2) {
                    ull c0 = cg2[j], c1 = cg2[j + 1];
                    ffma2(a0A, W0c[j], c0); ffma2(a0B, W0c[j + 1], c1);
                    ffma2(a1A, W1c[j], c0); ffma2(a1B, W1c[j + 1], c1);
                }
                float2 p = unpack2(a0A), q = unpack2(a0B);
                s_base[r * 64 + la] = (p.x + q.x) + (p.y + q.y);
                p = unpack2(a1A); q = unpack2(a1B);
                s_base[r * 64 + la + 32] = (p.x + q.x) + (p.y + q.y);
            }
            __syncwarp();
            // ---- D2+D3: temporal scores + softmax (warp) -> beta ----
            {
                const float* pp = g_proj + ((size_t)(b0 + r)) * ATT * Tt;
                const float* bg = s_base + r * 64;
                float ac0 = vd_b_r, ac1 = vd_b_r;
                #pragma unroll 4
                for (int a = 0; a < 64; ++a) {
                    float dca = bg[a];
                    float vw = s_vdw[a];
                    float p0 = pp[a * 64 + la];
                    float p1 = pp[a * 64 + la + 32];
                    ac0 = fmaf(vw, tanh_fast(p0 + dca), ac0);
                    ac1 = fmaf(vw, tanh_fast(p1 + dca), ac1);
                }
                float m = fmaxf(ac0, ac1);
                #pragma unroll
                for (int o = 16; o; o >>= 1) m = fmaxf(m, __shfl_xor_sync(0xffffffffu, m, o));
                float e0 = __expf(ac0 - m), e1 = __expf(ac1 - m);
                float ss = e0 + e1;
                #pragma unroll
                for (int o = 16; o; o >>= 1) ss += __shfl_xor_sync(0xffffffffu, ss, o);
                float inv = 1.f / ss;
                s_sc[r * 64 + la]      = e0 * inv;
                s_sc[r * 64 + la + 32] = e1 * inv;
            }
            __syncwarp();
            // ---- D4: context -> s_x (4 units per lane, float4) ----
            {
                const int u4 = 4 * la;
                const float4* hp4 = (const float4*)(g_hid + ((size_t)(b0 + r) * Tt) * Hh + u4);
                const float* be = s_sc + r * 64;
                float4 acc = make_float4(0.f, 0.f, 0.f, 0.f);
                #pragma unroll 4
                for (int tt = 0; tt < 64; ++tt) {
                    float b = be[tt];
                    float4 hv = hp4[tt * 32];
                    acc.x = fmaf(b, hv.x, acc.x);
                    acc.y = fmaf(b, hv.y, acc.y);
                    acc.z = fmaf(b, hv.z, acc.z);
                    acc.w = fmaf(b, hv.w, acc.w);
                }
                *(float4*)(s_x + r * 128 + u4) = acc;
            }
        } else if (wrp >= 8) {
            // ---- D5: Whh_dec · h -> s_gB (full k=128) ----
            ull acc[GN];
            #pragma unroll
            for (int g = 0; g < GN; ++g) acc[g] = 0ULL;
            #pragma unroll 2
            for (int kp = 0; kp < 64; ++kp) {
                ull w0 = WhhPd[(2 * kp) * 256 + gt];
                ull w1 = WhhPd[(2 * kp + 1) * 256 + gt];
                #pragma unroll
                for (int g = 0; g < GN; ++g) {
                    ulonglong2 hp = *(const ulonglong2*)(s_hd + g * 256 + 4 * kp);
                    ffma2(acc[g], w0, hp.x);
                    ffma2(acc[g], w1, hp.y);
                }
            }
            #pragma unroll
            for (int g = 0; g < GN; ++g) {
                float2 r2 = unpack2(acc[g]);
                *(float2*)(s_gB + g * 512 + 2 * gt) = r2;
            }
        }
        __syncthreads();
        // ---- D6: LSTM update (gB + bias + dWih*y_prev) ----
        if (gU < GN) {
            const float2* gB2 = (const float2*)(s_gB + gU * 512);
            const float2* b2  = (const float2*)s_bias;
            const float2* w2p = (const float2*)s_dWih;
            const int h2i = i2 >> 1;
            float y = s_yprev[gU];
            float pre[4][2];
            #pragma unroll
            for (int q = 0; q < 4; ++q) {
                int idx = q * 64 + h2i;
                float2 vB = gB2[idx], vb = b2[idx], vw = w2p[idx];
                pre[q][0] = fmaf(vw.x, y, vB.x + vb.x);
                pre[q][1] = fmaf(vw.y, y, vB.y + vb.y);
            }
            float hh[2];
            #pragma unroll
            for (int j = 0; j < 2; ++j) {
                float ig = sigm(pre[0][j]);
                float fg = sigm(pre[1][j]);
                float gv = tanh_acc(pre[2][j]);
                float og = sigm(pre[3][j]);
                float c2 = fmaf(fg, s_c[gU * 128 + i2 + j], ig * gv);
                float h2 = og * tanh_acc(c2);
                s_c[gU * 128 + i2 + j] = c2;
                s_h[gU * 128 + i2 + j] = h2;
                hh[j] = h2;
            }
            *(float4*)(s_hd + gU * 256 + 2 * i2) = make_float4(hh[0], hh[0], hh[1], hh[1]);
        }
        __syncthreads();
    }
    // final output step
    if (wrp < GN) do_D7(HOR - 1);
}

__global__ void __launch_bounds__(NTHR, 1)
darnn_kernel(const float* __restrict__ X,        const float* __restrict__ y_hist,
             const float* __restrict__ We_w,     const float* __restrict__ We_b,
             const float* __restrict__ ve_w,     const float* __restrict__ ve_b,
             const float* __restrict__ enc_bih,  const float* __restrict__ enc_bhh,
             const float* __restrict__ dec_Wih,  const float* __restrict__ dec_bih,
             const float* __restrict__ dec_bhh,
             const float* __restrict__ Wd_w,     const float* __restrict__ Wd_b,
             const float* __restrict__ vd_w,     const float* __restrict__ vd_b,
             const float* __restrict__ fc_w,     const float* __restrict__ fc_b,
             float* __restrict__ out) {
    extern __shared__ float sm[];
    if (blockIdx.x < NC7) {
        darnn_body<7>(blockIdx.x * 7,
                      X, y_hist, We_w, We_b, ve_w, ve_b, enc_bih, enc_bhh,
                      dec_Wih, dec_bih, dec_bhh, Wd_w, Wd_b, vd_w, vd_b,
                      fc_w, fc_b, out, sm);
    } else {
        darnn_body<6>(NC7 * 7 + (blockIdx.x - NC7) * 6,
                      X, y_hist, We_w, We_b, ve_w, ve_b, enc_bih, enc_bhh,
                      dec_Wih, dec_bih, dec_bhh, Wd_w, Wd_b, vd_w, vd_b,
                      fc_w, fc_b, out, sm);
    }
}

extern "C" void kernel_launch(void* const* d_in, const int* in_sizes, int n_in,
                              void* d_out, int out_size) {
    const float* X        = (const float*)d_in[0];
    const float* y_hist   = (const float*)d_in[1];
    const float* We_w     = (const float*)d_in[2];
    const float* We_b     = (const float*)d_in[3];
    const float* ve_w     = (const float*)d_in[4];
    const float* ve_b     = (const float*)d_in[5];
    const float* enc_Wih  = (const float*)d_in[6];
    const float* enc_Whh  = (const float*)d_in[7];
    const float* enc_bih  = (const float*)d_in[8];
    const float* enc_bhh  = (const float*)d_in[9];
    const float* dec_Wih  = (const float*)d_in[10];
    const float* dec_Whh  = (const float*)d_in[11];
    const float* dec_bih  = (const float*)d_in[12];
    const float* dec_bhh  = (const float*)d_in[13];
    const float* Wd_w     = (const float*)d_in[14];
    const float* Wd_b     = (const float*)d_in[15];
    const float* vd_w     = (const float*)d_in[16];
    const float* vd_b     = (const float*)d_in[17];
    const float* fc_w     = (const float*)d_in[18];
    const float* fc_b     = (const float*)d_in[19];
    float* out = (float*)d_out;

    cudaFuncSetAttribute(darnn_kernel,
                         cudaFuncAttributeMaxDynamicSharedMemorySize, SMEM_BYTES);

    transpose_k<<<(512 * 128 + 255) / 256, 256>>>(enc_Wih, enc_Whh, dec_Whh);
    darnn_kernel<<<NCTAS, NTHR, SMEM_BYTES>>>(
        X, y_hist, We_w, We_b, ve_w, ve_b,
        enc_bih, enc_bhh, dec_Wih, dec_bih, dec_bhh,
        Wd_w, Wd_b, vd_w, vd_b, fc_w, fc_b, out);
}